// round 1
// baseline (speedup 1.0000x reference)
#include <cuda_runtime.h>
#include <mma.h>

using namespace nvcuda;

#define CH   256
#define KOFF 27
#define MAXN 100000
#define TM   64
#define LDA  20     // A smem stride (floats): 16 + 4 pad
#define LDB  260    // B smem stride: 256 + 4 pad
#define LDO  132    // out smem stride: 128 + 4 pad
#define STATS_BLOCKS 512

// Scratch (device globals: allocation-free per harness rules)
__device__ float g_h[(size_t)MAXN * CH];     // bn_relu output
__device__ float g_y[(size_t)MAXN * CH];     // conv1 output
__device__ float g_part[2 * STATS_BLOCKS * CH];
__device__ float g_scale[CH];
__device__ float g_shift[CH];

// ---------------- BatchNorm stats (deterministic two-pass) ----------------

__global__ void bn_stats_kernel(const float* __restrict__ x, int n) {
    int c = threadIdx.x;
    float s = 0.f, s2 = 0.f;
    for (int r = blockIdx.x; r < n; r += gridDim.x) {
        float v = x[(size_t)r * CH + c];
        s += v;
        s2 += v * v;
    }
    g_part[blockIdx.x * CH + c] = s;
    g_part[STATS_BLOCKS * CH + blockIdx.x * CH + c] = s2;
}

__global__ void bn_finalize_kernel(const float* __restrict__ gamma,
                                   const float* __restrict__ beta, int n) {
    int c = threadIdx.x;
    float s = 0.f, s2 = 0.f;
    for (int b = 0; b < STATS_BLOCKS; b++) {
        s  += g_part[b * CH + c];
        s2 += g_part[STATS_BLOCKS * CH + b * CH + c];
    }
    float mean = s / (float)n;
    float var  = s2 / (float)n - mean * mean;
    float rstd = rsqrtf(var + 1e-4f);
    float sc = gamma[c] * rstd;
    g_scale[c] = sc;
    g_shift[c] = beta[c] - mean * sc;
}

__global__ void bn_apply_kernel(const float* __restrict__ x, float* __restrict__ y, int n) {
    size_t total4 = (size_t)n * CH / 4;
    for (size_t i = (size_t)blockIdx.x * blockDim.x + threadIdx.x; i < total4;
         i += (size_t)gridDim.x * blockDim.x) {
        int c0 = (int)(i & (CH / 4 - 1)) * 4;
        float4 v  = ((const float4*)x)[i];
        float4 sc = *(const float4*)(g_scale + c0);
        float4 sh = *(const float4*)(g_shift + c0);
        float4 r;
        r.x = fmaxf(fmaf(v.x, sc.x, sh.x), 0.f);
        r.y = fmaxf(fmaf(v.y, sc.y, sh.y), 0.f);
        r.z = fmaxf(fmaf(v.z, sc.z, sh.z), 0.f);
        r.w = fmaxf(fmaf(v.w, sc.w, sh.w), 0.f);
        ((float4*)y)[i] = r;
    }
}

// ---------------- Submanifold sparse conv: implicit GEMM, wmma tf32 --------
// Block tile: 64 points x 256 out-channels (full Cout: each gathered neighbor
// row is read exactly once). 8 warps, warp tile 64x32 (4x2 wmma 16x16k8 frags).

__device__ __forceinline__ float4 tf32_round4(float4 v) {
    v.x = wmma::__float_to_tf32(v.x);
    v.y = wmma::__float_to_tf32(v.y);
    v.z = wmma::__float_to_tf32(v.z);
    v.w = wmma::__float_to_tf32(v.w);
    return v;
}

__global__ __launch_bounds__(256, 2)
void conv_kernel(const float* __restrict__ x, const float* __restrict__ W,
                 const int* __restrict__ nbr, const float* __restrict__ resid,
                 float* __restrict__ out, int n)
{
    __shared__ __align__(128) float smem[TM * LDO];   // 8448 floats (33.8 KB), aliased
    float* As = smem;                                  // [64][LDA]
    float* Bs = smem + TM * LDA;                       // [16][LDB]
    __shared__ int nb_s[TM];

    const int tid  = threadIdx.x;
    const int warp = tid >> 5;
    const int m0   = blockIdx.x * TM;

    wmma::fragment<wmma::accumulator, 16, 16, 8, float> acc[4][2];
#pragma unroll
    for (int i = 0; i < 4; i++)
#pragma unroll
        for (int j = 0; j < 2; j++) wmma::fill_fragment(acc[i][j], 0.f);

    const int ar  = tid >> 2;          // A gather: row per 4 threads
    const int ac  = (tid & 3) * 4;     // 4 floats per thread
    const int br  = tid >> 4;          // B load: 16 rows x 16 threads
    const int btc = tid & 15;

    for (int k = 0; k < KOFF; k++) {
        __syncthreads();
        if (tid < TM) {
            int p = m0 + tid;
            nb_s[tid] = (p < n) ? nbr[p * KOFF + k] : -1;
        }
        __syncthreads();
        const float* Wk = W + (size_t)k * CH * CH;
        const int nb = nb_s[ar];
        const float4* xrow = (nb >= 0) ? (const float4*)(x + (size_t)nb * CH) : (const float4*)0;

        for (int kc = 0; kc < CH; kc += 16) {
            // stage A: gathered neighbor features (zero if missing), tf32-rounded
            float4 va = make_float4(0.f, 0.f, 0.f, 0.f);
            if (nb >= 0) va = xrow[(kc + ac) >> 2];
            *(float4*)(As + ar * LDA + ac) = tf32_round4(va);

            // stage B: W[k][kc:kc+16, 0:256]
            const float4* bsrc = (const float4*)(Wk + (size_t)(kc + br) * CH);
            float4* bdst = (float4*)(Bs + br * LDB);
#pragma unroll
            for (int i = 0; i < 4; i++)
                bdst[btc + i * 16] = tf32_round4(bsrc[btc + i * 16]);

            __syncthreads();

#pragma unroll
            for (int kk = 0; kk < 16; kk += 8) {
                wmma::fragment<wmma::matrix_a, 16, 16, 8, wmma::precision::tf32, wmma::row_major> af[4];
                wmma::fragment<wmma::matrix_b, 16, 16, 8, wmma::precision::tf32, wmma::row_major> bf[2];
#pragma unroll
                for (int i = 0; i < 4; i++)
                    wmma::load_matrix_sync(af[i], As + i * 16 * LDA + kk, LDA);
#pragma unroll
                for (int j = 0; j < 2; j++)
                    wmma::load_matrix_sync(bf[j], Bs + kk * LDB + warp * 32 + j * 16, LDB);
#pragma unroll
                for (int i = 0; i < 4; i++)
#pragma unroll
                    for (int j = 0; j < 2; j++)
                        wmma::mma_sync(acc[i][j], af[i], bf[j], acc[i][j]);
            }
            __syncthreads();
        }
    }

    // Epilogue via smem (handles ragged last tile + fused residual add), two
    // 128-column halves to fit the aliased smem buffer.
    const int orow = tid >> 2;
    for (int half = 0; half < 2; half++) {
        if ((warp >> 2) == half) {
            int wc = (warp & 3) * 32;
#pragma unroll
            for (int i = 0; i < 4; i++)
#pragma unroll
                for (int j = 0; j < 2; j++)
                    wmma::store_matrix_sync(smem + i * 16 * LDO + wc + j * 16,
                                            acc[i][j], LDO, wmma::mem_row_major);
        }
        __syncthreads();
        int p = m0 + orow;
        if (p < n) {
#pragma unroll
            for (int i = 0; i < 8; i++) {
                int cc = (tid & 3) * 4 + i * 16;
                float4 v = *(float4*)(smem + orow * LDO + cc);
                int gc = half * 128 + cc;
                if (resid) {
                    float4 rv = *(const float4*)(resid + (size_t)p * CH + gc);
                    v.x += rv.x; v.y += rv.y; v.z += rv.z; v.w += rv.w;
                }
                *(float4*)(out + (size_t)p * CH + gc) = v;
            }
        }
        __syncthreads();
    }
}

// ---------------- launch ----------------

extern "C" void kernel_launch(void* const* d_in, const int* in_sizes, int n_in,
                              void* d_out, int out_size) {
    const float* feat   = (const float*)d_in[0];
    // d_in[1] = pos (unused)
    const int*   nbr    = (const int*)d_in[2];
    const float* W1     = (const float*)d_in[3];
    const float* gamma1 = (const float*)d_in[4];
    const float* beta1  = (const float*)d_in[5];
    const float* W2     = (const float*)d_in[6];
    const float* gamma2 = (const float*)d_in[7];
    const float* beta2  = (const float*)d_in[8];
    float* out = (float*)d_out;

    int n = in_sizes[0] / CH;
    if (n <= 0) return;

    float *h, *y;
    cudaGetSymbolAddress((void**)&h, g_h);
    cudaGetSymbolAddress((void**)&y, g_y);

    int cb = (n + TM - 1) / TM;

    // stage 1: h = bn_relu(feat)
    bn_stats_kernel<<<STATS_BLOCKS, 256>>>(feat, n);
    bn_finalize_kernel<<<1, 256>>>(gamma1, beta1, n);
    bn_apply_kernel<<<2048, 256>>>(feat, h, n);
    // y = subconv(h, W1)
    conv_kernel<<<cb, 256>>>(h, W1, nbr, (const float*)0, y, n);
    // stage 2: h = bn_relu(y)
    bn_stats_kernel<<<STATS_BLOCKS, 256>>>(y, n);
    bn_finalize_kernel<<<1, 256>>>(gamma2, beta2, n);
    bn_apply_kernel<<<2048, 256>>>(y, h, n);
    // out = feat + subconv(h, W2)
    conv_kernel<<<cb, 256>>>(h, W2, nbr, feat, out, n);
}

// round 3
// speedup vs baseline: 4.3672x; 4.3672x over previous
#include <cuda_runtime.h>
#include <cuda_fp16.h>
#include <mma.h>
#include <cstdint>

using namespace nvcuda;

#define CH    256
#define KOFF  27
#define MAXN  100000
#define BM    128      // points per CTA
#define BN    128      // cout per CTA (grid.y = 2)
#define KC    32       // K-chunk
#define STATS_BLOCKS 512

// smem layout (bytes, within dynamic buffer)
#define A_BUF_B   (128 * 40 * 2)          // 10240: 128 rows x (32+8 pad) halfs
#define B_BUF_B   (32 * 136 * 2)          // 8704:  32 rows x (128+8 pad) halfs
#define OFF_A     0
#define OFF_B     (2 * A_BUF_B)           // 20480
#define OFF_NB    (OFF_B + 2 * B_BUF_B)   // 37888
#define OFF_ESC   (OFF_NB + KOFF * BM * 4)// 51712
#define SMEM_TOT  (OFF_ESC + 8 * 16 * 20 * 4) // 61952

// ---- scratch (device globals; allocation-free) ----
__device__ __half g_h [(size_t)MAXN * CH];     // bn_relu output (fp16)
__device__ float  g_y [(size_t)MAXN * CH];     // conv1 output (fp32)
__device__ __half g_w1h[(size_t)KOFF * CH * CH];
__device__ __half g_w2h[(size_t)KOFF * CH * CH];
__device__ float  g_part[2 * STATS_BLOCKS * CH];
__device__ float  g_scale[CH];
__device__ float  g_shift[CH];

__device__ __forceinline__ uint32_t smem_u32(const void* p) {
    uint32_t a;
    asm("{ .reg .u64 t; cvta.to.shared.u64 t, %1; cvt.u32.u64 %0, t; }" : "=r"(a) : "l"(p));
    return a;
}
__device__ __forceinline__ void cp16(uint32_t dst, const void* src, int src_size) {
    asm volatile("cp.async.cg.shared.global [%0], [%1], 16, %2;"
                 :: "r"(dst), "l"(src), "r"(src_size) : "memory");
}
__device__ __forceinline__ void cp_commit() {
    asm volatile("cp.async.commit_group;" ::: "memory");
}
__device__ __forceinline__ void cp_wait1() {
    asm volatile("cp.async.wait_group 1;" ::: "memory");
}

// ---------------- BatchNorm ----------------
__global__ void bn_stats_kernel(const float* __restrict__ x, int n) {
    int c = threadIdx.x;
    float s = 0.f, s2 = 0.f;
    for (int r = blockIdx.x; r < n; r += gridDim.x) {
        float v = x[(size_t)r * CH + c];
        s += v; s2 += v * v;
    }
    g_part[blockIdx.x * CH + c] = s;
    g_part[STATS_BLOCKS * CH + blockIdx.x * CH + c] = s2;
}

__global__ void bn_finalize_kernel(const float* __restrict__ gamma,
                                   const float* __restrict__ beta, int n) {
    int c = threadIdx.x;
    float s = 0.f, s2 = 0.f;
    for (int b = 0; b < STATS_BLOCKS; b++) {
        s  += g_part[b * CH + c];
        s2 += g_part[STATS_BLOCKS * CH + b * CH + c];
    }
    float mean = s / (float)n;
    float var  = s2 / (float)n - mean * mean;
    float rstd = rsqrtf(var + 1e-4f);
    float sc = gamma[c] * rstd;
    g_scale[c] = sc;
    g_shift[c] = beta[c] - mean * sc;
}

// bn + relu, output fp16
__global__ void bn_apply_kernel(const float* __restrict__ x, __half* __restrict__ y, int n) {
    size_t total4 = (size_t)n * CH / 4;
    for (size_t i = (size_t)blockIdx.x * blockDim.x + threadIdx.x; i < total4;
         i += (size_t)gridDim.x * blockDim.x) {
        int c0 = (int)(i & (CH / 4 - 1)) * 4;
        float4 v  = ((const float4*)x)[i];
        float4 sc = *(const float4*)(g_scale + c0);
        float4 sh = *(const float4*)(g_shift + c0);
        float a = fmaxf(fmaf(v.x, sc.x, sh.x), 0.f);
        float b = fmaxf(fmaf(v.y, sc.y, sh.y), 0.f);
        float c = fmaxf(fmaf(v.z, sc.z, sh.z), 0.f);
        float d = fmaxf(fmaf(v.w, sc.w, sh.w), 0.f);
        __half2* y2 = (__half2*)(y + i * 4);
        y2[0] = __floats2half2_rn(a, b);
        y2[1] = __floats2half2_rn(c, d);
    }
}

// weights fp32 -> fp16 (layout already [k][cin][cout] = B row-major)
__global__ void w2h_kernel(const float* __restrict__ W, __half* __restrict__ Wh, int total) {
    for (int i = blockIdx.x * blockDim.x + threadIdx.x; i < total;
         i += gridDim.x * blockDim.x)
        Wh[i] = __float2half_rn(W[i]);
}

// ---------------- fp16 implicit-GEMM sparse conv ----------------
// CTA: 128 points x 128 cout (grid.y=2 halves). 8 warps, warp tile 32x64.
// 216 K-chunks of 32, cp.async double-buffered; neighbor idx pre-staged.
__global__ __launch_bounds__(256, 2)
void conv_mma(const __half* __restrict__ x, const __half* __restrict__ W,
              const int* __restrict__ nbr, const float* __restrict__ resid,
              float* __restrict__ out, int n)
{
    extern __shared__ char dyn[];
    const int tid  = threadIdx.x;
    const int wid  = tid >> 5;
    const int lane = tid & 31;
    const int m0   = blockIdx.x * BM;
    const int co0  = blockIdx.y * BN;

    int* nb_s = (int*)(dyn + OFF_NB);
    const uint32_t a_u = smem_u32(dyn + OFF_A);
    const uint32_t b_u = smem_u32(dyn + OFF_B);

    // pre-stage all 27x128 neighbor indices
    for (int i = tid; i < KOFF * BM; i += 256) {
        int k = i >> 7, r = i & 127;
        int p = m0 + r;
        nb_s[i] = (p < n) ? nbr[p * KOFF + k] : -1;
    }
    __syncthreads();

    wmma::fragment<wmma::accumulator, 16, 16, 16, float> acc[2][4];
#pragma unroll
    for (int i = 0; i < 2; i++)
#pragma unroll
        for (int j = 0; j < 4; j++) wmma::fill_fragment(acc[i][j], 0.f);

    const int wm = wid & 3;      // M group: 32 rows
    const int wn = wid >> 2;     // N group: 64 cols

    const int CHUNKS = KOFF * CH / KC;   // 216

    // ---- staging lambda (manual) ----
    // A: 512 16B-chunks (idx: row=idx>>2, c16=idx&3); B: 512 (row=idx>>4, c16=idx&15)
    auto stage = [&](int c) {
        int buf = c & 1;
        int kct = c * KC;
        int k   = kct >> 8;
        int kc  = kct & 255;
        const __half* wk = W + (size_t)k * CH * CH;
#pragma unroll
        for (int i = 0; i < 2; i++) {
            int idx = tid + i * 256;
            int row = idx >> 2, c16 = idx & 3;
            int nb = nb_s[k * BM + row];
            uint32_t dst = a_u + buf * A_BUF_B + row * 80 + c16 * 16;
            const __half* src = x + ((size_t)(nb < 0 ? 0 : nb) * CH + kc + c16 * 8);
            cp16(dst, src, nb < 0 ? 0 : 16);
        }
#pragma unroll
        for (int i = 0; i < 2; i++) {
            int idx = tid + i * 256;
            int row = idx >> 4, c16 = idx & 15;
            uint32_t dst = b_u + buf * B_BUF_B + row * 272 + c16 * 16;
            const __half* src = wk + ((size_t)(kc + row) * CH + co0 + c16 * 8);
            cp16(dst, src, 16);
        }
    };

    stage(0);
    cp_commit();

    for (int c = 0; c < CHUNKS; c++) {
        if (c + 1 < CHUNKS) stage(c + 1);
        cp_commit();
        cp_wait1();
        __syncthreads();

        const __half* A = (const __half*)(dyn + OFF_A + (c & 1) * A_BUF_B);
        const __half* B = (const __half*)(dyn + OFF_B + (c & 1) * B_BUF_B);
#pragma unroll
        for (int kk = 0; kk < KC; kk += 16) {
            wmma::fragment<wmma::matrix_a, 16, 16, 16, __half, wmma::row_major> af[2];
            wmma::fragment<wmma::matrix_b, 16, 16, 16, __half, wmma::row_major> bf[4];
#pragma unroll
            for (int i = 0; i < 2; i++)
                wmma::load_matrix_sync(af[i], A + (wm * 32 + i * 16) * 40 + kk, 40);
#pragma unroll
            for (int j = 0; j < 4; j++)
                wmma::load_matrix_sync(bf[j], B + kk * 136 + wn * 64 + j * 16, 136);
#pragma unroll
            for (int i = 0; i < 2; i++)
#pragma unroll
                for (int j = 0; j < 4; j++)
                    wmma::mma_sync(acc[i][j], af[i], bf[j], acc[i][j]);
        }
        __syncthreads();
    }

    // ---- epilogue: 16x16 tiles; direct global store (n%16==0 => tiles all-or-nothing),
    // partial-tile fallback via per-warp smem scratch.
    float* esc = (float*)(dyn + OFF_ESC) + wid * 16 * 20;
#pragma unroll
    for (int i = 0; i < 2; i++) {
        int row0 = m0 + wm * 32 + i * 16;
        if (row0 >= n) continue;
#pragma unroll
        for (int j = 0; j < 4; j++) {
            int col0 = co0 + wn * 64 + j * 16;
            if (row0 + 16 <= n) {
                if (resid) {
                    wmma::fragment<wmma::accumulator, 16, 16, 16, float> rf;
                    wmma::load_matrix_sync(rf, resid + (size_t)row0 * CH + col0, CH,
                                           wmma::mem_row_major);
#pragma unroll
                    for (int e = 0; e < rf.num_elements; e++) acc[i][j].x[e] += rf.x[e];
                }
                wmma::store_matrix_sync(out + (size_t)row0 * CH + col0, acc[i][j], CH,
                                        wmma::mem_row_major);
            } else {
                wmma::store_matrix_sync(esc, acc[i][j], 20, wmma::mem_row_major);
                __syncwarp();
                for (int e = lane; e < 256; e += 32) {
                    int r = e >> 4, cc = e & 15;
                    int p = row0 + r;
                    if (p < n) {
                        float v = esc[r * 20 + cc];
                        if (resid) v += resid[(size_t)p * CH + col0 + cc];
                        out[(size_t)p * CH + col0 + cc] = v;
                    }
                }
                __syncwarp();
            }
        }
    }
}

// ---------------- launch ----------------
extern "C" void kernel_launch(void* const* d_in, const int* in_sizes, int n_in,
                              void* d_out, int out_size) {
    const float* feat   = (const float*)d_in[0];
    const int*   nbr    = (const int*)d_in[2];
    const float* W1     = (const float*)d_in[3];
    const float* gamma1 = (const float*)d_in[4];
    const float* beta1  = (const float*)d_in[5];
    const float* W2     = (const float*)d_in[6];
    const float* gamma2 = (const float*)d_in[7];
    const float* beta2  = (const float*)d_in[8];
    float* out = (float*)d_out;

    int n = in_sizes[0] / CH;
    if (n <= 0) return;

    __half *h, *wh1, *wh2;
    float *y;
    cudaGetSymbolAddress((void**)&h,   g_h);
    cudaGetSymbolAddress((void**)&y,   g_y);
    cudaGetSymbolAddress((void**)&wh1, g_w1h);
    cudaGetSymbolAddress((void**)&wh2, g_w2h);

    cudaFuncSetAttribute(conv_mma, cudaFuncAttributeMaxDynamicSharedMemorySize, SMEM_TOT);

    const int WTOT = KOFF * CH * CH;
    w2h_kernel<<<512, 256>>>(W1, wh1, WTOT);
    w2h_kernel<<<512, 256>>>(W2, wh2, WTOT);

    dim3 cgrid((n + BM - 1) / BM, 2);

    bn_stats_kernel<<<STATS_BLOCKS, 256>>>(feat, n);
    bn_finalize_kernel<<<1, 256>>>(gamma1, beta1, n);
    bn_apply_kernel<<<2048, 256>>>(feat, h, n);
    conv_mma<<<cgrid, 256, SMEM_TOT>>>(h, wh1, nbr, (const float*)0, y, n);

    bn_stats_kernel<<<STATS_BLOCKS, 256>>>(y, n);
    bn_finalize_kernel<<<1, 256>>>(gamma2, beta2, n);
    bn_apply_kernel<<<2048, 256>>>(y, h, n);
    conv_mma<<<cgrid, 256, SMEM_TOT>>>(h, wh2, nbr, feat, out, n);
}